// round 1
// baseline (speedup 1.0000x reference)
#include <cuda_runtime.h>
#include <cuda_bf16.h>
#include <math.h>

// ---------------- problem constants ----------------
#define D_MODEL   1024
#define D_INNER   2048
#define D_STATE   64
#define HEADDIM   128
#define NHEADS    16
#define D_CONV    4
#define CONV_DIM  2176            // D_INNER + 2*D_STATE
#define D_IN_PROJ 4240            // 2*D_INNER + 2*D_STATE + NHEADS
#define BATCH     2
#define SEQLEN    4096
#define NROWS     (BATCH*SEQLEN)  // 8192
#define RMS_EPS   1e-5f

// ---------------- scratch (static device globals, no runtime alloc) -------
__device__ float g_zx [(size_t)NROWS * D_IN_PROJ];   // in_proj output  (139 MB)
__device__ float g_xbc[(size_t)NROWS * CONV_DIM];    // conv+silu out   (71 MB)
__device__ float g_dec[(size_t)NROWS * NHEADS];      // exp(softplus(dt)*A)
__device__ float g_y  [(size_t)NROWS * D_INNER];     // scan output + D*x
__device__ float g_yg [(size_t)NROWS * D_INNER];     // after rmsnorm+gate

// ---------------- GEMM: C[m,n] = sum_k A[m,k]*B[n,k]  (both row-major, K-contig)
#define BM 128
#define BN 128
#define BKT 16
#define TM 8
#define TN 8

__global__ __launch_bounds__(256) void gemm_nt(
    const float* __restrict__ A, const float* __restrict__ B,
    float* __restrict__ C, int M, int N, int K)
{
    __shared__ float As[BKT][BM + 4];
    __shared__ float Bs[BKT][BN + 4];

    const int tid = threadIdx.x;
    const int tx  = tid & 15;      // 0..15 -> col frags
    const int ty  = tid >> 4;      // 0..15 -> row frags
    const int bm  = blockIdx.y * BM;
    const int bn  = blockIdx.x * BN;

    float acc[TM][TN];
    #pragma unroll
    for (int i = 0; i < TM; i++)
        #pragma unroll
        for (int j = 0; j < TN; j++) acc[i][j] = 0.f;

    for (int kt = 0; kt < K; kt += BKT) {
        // load A tile (BM x BKT), coalesced over k, transposed into As[k][m]
        #pragma unroll
        for (int i = 0; i < 8; i++) {
            int idx = tid + i * 256;
            int k = idx & (BKT - 1);
            int m = idx >> 4;
            int gm = bm + m;
            As[k][m] = (gm < M) ? A[(size_t)gm * K + kt + k] : 0.f;
        }
        // load B tile (BN x BKT) -> Bs[k][n]
        #pragma unroll
        for (int i = 0; i < 8; i++) {
            int idx = tid + i * 256;
            int k = idx & (BKT - 1);
            int n = idx >> 4;
            int gn = bn + n;
            Bs[k][n] = (gn < N) ? B[(size_t)gn * K + kt + k] : 0.f;
        }
        __syncthreads();

        #pragma unroll
        for (int k = 0; k < BKT; k++) {
            float a[TM], b[TN];
            #pragma unroll
            for (int i = 0; i < TM; i += 4)
                *(float4*)&a[i] = *(const float4*)&As[k][ty * TM + i];
            #pragma unroll
            for (int j = 0; j < TN; j += 4)
                *(float4*)&b[j] = *(const float4*)&Bs[k][tx * TN + j];
            #pragma unroll
            for (int i = 0; i < TM; i++)
                #pragma unroll
                for (int j = 0; j < TN; j++)
                    acc[i][j] = fmaf(a[i], b[j], acc[i][j]);
        }
        __syncthreads();
    }

    // store
    #pragma unroll
    for (int i = 0; i < TM; i++) {
        int gm = bm + ty * TM + i;
        if (gm >= M) continue;
        size_t row = (size_t)gm * N;
        #pragma unroll
        for (int j = 0; j < TN; j += 4) {
            int gn = bn + tx * TN + j;
            if (gn + 3 < N) {
                float4 v = make_float4(acc[i][j], acc[i][j+1], acc[i][j+2], acc[i][j+3]);
                *(float4*)&C[row + gn] = v;
            } else {
                #pragma unroll
                for (int jj = 0; jj < 4; jj++)
                    if (gn + jj < N) C[row + gn + jj] = acc[i][j + jj];
            }
        }
    }
}

// ---------------- depthwise causal conv (k=4) + bias + SiLU ----------------
__global__ __launch_bounds__(256) void conv_kernel(
    const float* __restrict__ zx, const float* __restrict__ cw,
    const float* __restrict__ cb, float* __restrict__ xbc)
{
    int c = blockIdx.x * 256 + threadIdx.x;
    if (c >= CONV_DIM) return;
    int strip = blockIdx.y;         // 16 strips of 256
    int b     = blockIdx.z;
    int l0    = strip * 256;

    float w0 = cw[c*4+0], w1 = cw[c*4+1], w2 = cw[c*4+2], w3 = cw[c*4+3];
    float bias = cb[c];

    size_t colbase = (size_t)D_INNER + c;          // xBC starts at col 2048
    size_t rb = (size_t)b * SEQLEN;

    float xm3 = (l0-3 >= 0) ? zx[(rb + l0-3) * D_IN_PROJ + colbase] : 0.f;
    float xm2 = (l0-2 >= 0) ? zx[(rb + l0-2) * D_IN_PROJ + colbase] : 0.f;
    float xm1 = (l0-1 >= 0) ? zx[(rb + l0-1) * D_IN_PROJ + colbase] : 0.f;

    for (int l = l0; l < l0 + 256; l++) {
        float xv = zx[(rb + l) * D_IN_PROJ + colbase];
        float a = bias;
        a = fmaf(w0, xm3, a);
        a = fmaf(w1, xm2, a);
        a = fmaf(w2, xm1, a);
        a = fmaf(w3, xv,  a);
        float sv = a / (1.f + expf(-a));
        xbc[(rb + l) * CONV_DIM + c] = sv;
        xm3 = xm2; xm2 = xm1; xm1 = xv;
    }
}

// ---------------- dt -> softplus -> decay = exp(A * softplus(dt)) ----------
__global__ __launch_bounds__(256) void decay_kernel(
    const float* __restrict__ zx, const float* __restrict__ dt_bias,
    const float* __restrict__ A_log, float* __restrict__ dec)
{
    int idx = blockIdx.x * 256 + threadIdx.x;
    if (idx >= NROWS * NHEADS) return;
    int r = idx >> 4;
    int h = idx & 15;
    float raw = zx[(size_t)r * D_IN_PROJ + (D_IN_PROJ - NHEADS) + h] + dt_bias[h];
    float sp  = (raw > 20.f) ? raw : log1pf(expf(raw));
    float A   = -expf(A_log[h]);
    dec[idx]  = expf(sp * A);
}

// ---------------- sequential SSM scan ------------------------------------
// grid (4 p-slices, 16 heads, 2 batch), 128 threads.
// thread: pl = tid>>2 (p within slice), nq = tid&3 (16-wide n slice).
__global__ __launch_bounds__(128) void scan_kernel(
    const float* __restrict__ xbc, const float* __restrict__ dec,
    const float* __restrict__ Dvec, float* __restrict__ yout)
{
    const int pb = blockIdx.x;   // 0..3
    const int h  = blockIdx.y;
    const int b  = blockIdx.z;
    const int tid = threadIdx.x;
    const int pl = tid >> 2;     // 0..31
    const int nq = tid & 3;      // 0..3

    __shared__ float sB[2][64], sC[2][64], sx[2][32];
    __shared__ float sdec[2];

    float s[16];
    #pragma unroll
    for (int j = 0; j < 16; j++) s[j] = 0.f;
    const float Dh = Dvec[h];

    const size_t base = (size_t)b * SEQLEN;
    const int xcol = h * HEADDIM + pb * 32;

    float r0 = 0.f, r1 = 0.f, rdec = 0.f;

    auto ld_regs = [&](int l) {
        size_t row = (base + l) * CONV_DIM;
        if (tid < 64)       r0 = xbc[row + D_INNER + tid];            // B
        else                r0 = xbc[row + D_INNER + 64 + (tid - 64)];// C
        if (tid < 32)       r1 = xbc[row + xcol + tid];               // x slice
        if (tid == 127)     rdec = dec[(base + l) * NHEADS + h];
    };
    auto sts = [&](int buf) {
        if (tid < 64)   sB[buf][tid] = r0;
        else            sC[buf][tid - 64] = r0;
        if (tid < 32)   sx[buf][tid] = r1;
        if (tid == 127) sdec[buf] = rdec;
    };

    ld_regs(0); sts(0);
    ld_regs(1);
    __syncthreads();

    for (int l = 0; l < SEQLEN; l++) {
        int cur = l & 1;
        if (l + 1 < SEQLEN) sts(cur ^ 1);     // stage l+1 into smem
        if (l + 2 < SEQLEN) ld_regs(l + 2);   // prefetch l+2 into regs

        float dcy = sdec[cur];
        float xv  = sx[cur][pl];
        const float4* B4 = (const float4*)&sB[cur][nq * 16];
        const float4* C4 = (const float4*)&sC[cur][nq * 16];

        float y = 0.f;
        #pragma unroll
        for (int q = 0; q < 4; q++) {
            float4 bq = B4[q];
            float4 cq = C4[q];
            s[q*4+0] = fmaf(s[q*4+0], dcy, bq.x * xv);  y = fmaf(s[q*4+0], cq.x, y);
            s[q*4+1] = fmaf(s[q*4+1], dcy, bq.y * xv);  y = fmaf(s[q*4+1], cq.y, y);
            s[q*4+2] = fmaf(s[q*4+2], dcy, bq.z * xv);  y = fmaf(s[q*4+2], cq.z, y);
            s[q*4+3] = fmaf(s[q*4+3], dcy, bq.w * xv);  y = fmaf(s[q*4+3], cq.w, y);
        }
        y += __shfl_xor_sync(0xffffffffu, y, 1);
        y += __shfl_xor_sync(0xffffffffu, y, 2);
        if (nq == 0)
            yout[(base + l) * D_INNER + xcol + pl] = fmaf(Dh, xv, y);
        __syncthreads();
    }
}

// ---------------- RMSNorm + sigmoid(z) gate --------------------------------
__global__ __launch_bounds__(256) void rms_gate_kernel(
    const float* __restrict__ y, const float* __restrict__ zx,
    const float* __restrict__ rmsw, float* __restrict__ yg)
{
    int r = blockIdx.x;
    const float*  yr = y  + (size_t)r * D_INNER;
    const float*  zr = zx + (size_t)r * D_IN_PROJ;   // z at cols [0,2048)
    const float4* y4 = (const float4*)yr;

    int tid = threadIdx.x;
    float ss = 0.f;
    #pragma unroll
    for (int i = 0; i < 2; i++) {
        float4 v = y4[tid + i * 256];
        ss += v.x*v.x + v.y*v.y + v.z*v.z + v.w*v.w;
    }
    #pragma unroll
    for (int o = 16; o > 0; o >>= 1) ss += __shfl_xor_sync(0xffffffffu, ss, o);
    __shared__ float red[8];
    if ((tid & 31) == 0) red[tid >> 5] = ss;
    __syncthreads();
    if (tid == 0) {
        float t = 0.f;
        #pragma unroll
        for (int i = 0; i < 8; i++) t += red[i];
        red[0] = rsqrtf(t * (1.f / D_INNER) + RMS_EPS);
    }
    __syncthreads();
    float rs = red[0];

    const float4* z4 = (const float4*)zr;
    const float4* w4 = (const float4*)rmsw;
    float4*       g4 = (float4*)(yg + (size_t)r * D_INNER);
    #pragma unroll
    for (int i = 0; i < 2; i++) {
        int c = tid + i * 256;
        float4 v = y4[c];
        float4 z = z4[c];
        float4 w = w4[c];
        float4 o;
        o.x = v.x * rs * w.x * (1.f / (1.f + expf(-z.x)));
        o.y = v.y * rs * w.y * (1.f / (1.f + expf(-z.y)));
        o.z = v.z * rs * w.z * (1.f / (1.f + expf(-z.z)));
        o.w = v.w * rs * w.w * (1.f / (1.f + expf(-z.w)));
        g4[c] = o;
    }
}

// ---------------- launcher -------------------------------------------------
extern "C" void kernel_launch(void* const* d_in, const int* in_sizes, int n_in,
                              void* d_out, int out_size)
{
    const float* u        = (const float*)d_in[0];  // [2,4096,1024]
    const float* in_proj  = (const float*)d_in[1];  // [4240,1024]
    const float* conv_w   = (const float*)d_in[2];  // [2176,4]
    const float* conv_b   = (const float*)d_in[3];  // [2176]
    const float* dt_bias  = (const float*)d_in[4];  // [16]
    const float* A_log    = (const float*)d_in[5];  // [16]
    const float* Dv       = (const float*)d_in[6];  // [16]
    const float* rms_w    = (const float*)d_in[7];  // [2048]
    const float* out_w    = (const float*)d_in[8];  // [1024,2048]
    float* out = (float*)d_out;

    float *zx, *xbc, *dec, *y, *yg;
    cudaGetSymbolAddress((void**)&zx,  g_zx);
    cudaGetSymbolAddress((void**)&xbc, g_xbc);
    cudaGetSymbolAddress((void**)&dec, g_dec);
    cudaGetSymbolAddress((void**)&y,   g_y);
    cudaGetSymbolAddress((void**)&yg,  g_yg);

    // 1) in_proj: zx[8192,4240] = u[8192,1024] @ in_proj^T
    {
        dim3 grid((D_IN_PROJ + BN - 1) / BN, NROWS / BM);
        gemm_nt<<<grid, 256>>>(u, in_proj, zx, NROWS, D_IN_PROJ, D_MODEL);
    }
    // 2) conv + silu on xBC part
    {
        dim3 grid((CONV_DIM + 255) / 256, SEQLEN / 256, BATCH);
        conv_kernel<<<grid, 256>>>(zx, conv_w, conv_b, xbc);
    }
    // 3) decay precompute
    decay_kernel<<<(NROWS * NHEADS + 255) / 256, 256>>>(zx, dt_bias, A_log, dec);
    // 4) SSM scan
    {
        dim3 grid(HEADDIM / 32, NHEADS, BATCH);
        scan_kernel<<<grid, 128>>>(xbc, dec, Dv, y);
    }
    // 5) rmsnorm + gate
    rms_gate_kernel<<<NROWS, 256>>>(y, zx, rms_w, yg);
    // 6) out_proj: out[8192,1024] = yg[8192,2048] @ out_w^T
    {
        dim3 grid(D_MODEL / BN, NROWS / BM);
        gemm_nt<<<grid, 256>>>(yg, out_w, out, NROWS, D_MODEL, D_INNER);
    }
}

// round 3
// speedup vs baseline: 2.2027x; 2.2027x over previous
#include <cuda_runtime.h>
#include <cuda_bf16.h>
#include <cstdint>
#include <math.h>

// ---------------- problem constants ----------------
#define D_MODEL   1024
#define D_INNER   2048
#define D_STATE   64
#define HEADDIM   128
#define NHEADS    16
#define D_CONV    4
#define CONV_DIM  2176            // D_INNER + 2*D_STATE
#define D_IN_PROJ 4240            // 2*D_INNER + 2*D_STATE + NHEADS
#define BATCH     2
#define SEQLEN    4096
#define NROWS     (BATCH*SEQLEN)  // 8192
#define RMS_EPS   1e-5f

// arch-specific (sm_103a) feature gate: tcgen05 only exists on the 'a' target
#if defined(__CUDA_ARCH_FEAT_SM103_ALL) || \
    (defined(__CUDA_ARCH_SPECIFIC__) && (__CUDA_ARCH_SPECIFIC__ == 1030))
#define HAVE_TCGEN05 1
#else
#define HAVE_TCGEN05 0
#endif

// ---------------- scratch (static device globals, no runtime alloc) -------
__device__ float g_zx [(size_t)NROWS * D_IN_PROJ];
__device__ float g_xbc[(size_t)NROWS * CONV_DIM];
__device__ float g_dec[(size_t)NROWS * NHEADS];
__device__ float g_y  [(size_t)NROWS * D_INNER];
__device__ float g_yg [(size_t)NROWS * D_INNER];

// ================= common helpers =================
__device__ __forceinline__ uint32_t smem_to_u32(const void* p) {
    uint32_t a;
    asm("{ .reg .u64 t; cvta.to.shared.u64 t, %1; cvt.u32.u64 %0, t; }"
        : "=r"(a) : "l"(p));
    return a;
}
__device__ __forceinline__ void split_tf32(float v, uint32_t& hi, uint32_t& lo) {
    float h, l;
    asm("cvt.rna.tf32.f32 %0, %1;" : "=f"(h) : "f"(v));
    float r = v - h;
    asm("cvt.rna.tf32.f32 %0, %1;" : "=f"(l) : "f"(r));
    hi = __float_as_uint(h);
    lo = __float_as_uint(l);
}
__device__ __forceinline__ void mma_16n8k8(float* d, const uint32_t* a,
                                           const uint32_t* b) {
    asm volatile(
        "mma.sync.aligned.m16n8k8.row.col.f32.tf32.tf32.f32 "
        "{%0,%1,%2,%3},{%4,%5,%6,%7},{%8,%9},{%0,%1,%2,%3};"
        : "+f"(d[0]), "+f"(d[1]), "+f"(d[2]), "+f"(d[3])
        : "r"(a[0]), "r"(a[1]), "r"(a[2]), "r"(a[3]), "r"(b[0]), "r"(b[1]));
}

#if HAVE_TCGEN05
// ---------- tcgen05 helpers (sm_103a only) ----------
__device__ __forceinline__ uint32_t elect_one_pred() {
    uint32_t pred;
    asm volatile(
        "{\n\t.reg .pred p;\n\telect.sync _|p, 0xFFFFFFFF;\n\t"
        "selp.b32 %0, 1, 0, p;\n\t}" : "=r"(pred));
    return pred;
}
#define SMEM_SWIZZLE_128B(bo) ((bo) ^ (((bo) >> 3) & 0x70))
static constexpr uint64_t SMEM_DESC_BASE_SW128 =
    (uint64_t(2) << 61) | (uint64_t(1) << 46) | (uint64_t(64) << 32) | (uint64_t(1) << 16);
#define MAKE_SMEM_DESC(base_addr) \
    (SMEM_DESC_BASE_SW128 | ((uint64_t)((base_addr) >> 4) & 0x3FFF))
#define TCGEN05_ALLOC(smem_result_addr, nCols) \
    asm volatile("tcgen05.alloc.cta_group::1.sync.aligned.shared::cta.b32 [%0], %1;" \
        :: "r"((uint32_t)(smem_result_addr)), "r"((uint32_t)(nCols)) : "memory")
#define TCGEN05_DEALLOC(tmem_addr, nCols) \
    asm volatile("tcgen05.dealloc.cta_group::1.sync.aligned.b32 %0, %1;" \
        :: "r"(tmem_addr), "r"((uint32_t)(nCols)))
#define TCGEN05_COMMIT(mbar_smem_addr) \
    asm volatile("tcgen05.commit.cta_group::1.mbarrier::arrive::one.shared::cluster.b64 [%0];" \
        :: "r"((uint32_t)(mbar_smem_addr)) : "memory")
#define TCGEN05_WAIT_LD() asm volatile("tcgen05.wait::ld.sync.aligned;" ::: "memory")
#define TCGEN05_FENCE_AFTER() asm volatile("tcgen05.fence::after_thread_sync;" ::: "memory")
#define TCGEN05_FENCE_BEFORE() asm volatile("tcgen05.fence::before_thread_sync;" ::: "memory")
#define FENCE_PROXY_ASYNC_SHARED_CTA() \
    asm volatile("fence.proxy.async.shared::cta;" ::: "memory")
#define MBARRIER_INIT(mbar_smem_addr, count) \
    asm volatile("mbarrier.init.shared.b64 [%0], %1;" \
        :: "r"((uint32_t)(mbar_smem_addr)), "r"((uint32_t)(count)) : "memory")
#define MBARRIER_WAIT_PARITY(mbar_smem_addr, phase_parity) do { \
    uint32_t _mbar = (uint32_t)(mbar_smem_addr); \
    uint32_t _parity = (uint32_t)(phase_parity); \
    uint32_t _done; \
    asm volatile( \
        "{\n\t.reg .pred p;\n\t" \
        "mbarrier.try_wait.parity.acquire.cta.shared::cta.b64 p, [%1], %2;\n\t" \
        "selp.b32 %0, 1, 0, p;\n\t}" \
        : "=r"(_done) : "r"(_mbar), "r"(_parity) : "memory"); \
    if (!_done) { \
        asm volatile( \
            "{\n\t.reg .pred P1;\n\t" \
            "WAIT_LOOP_%=:\n\t" \
            "mbarrier.try_wait.parity.acquire.cta.shared::cta.b64 P1, [%0], %1, 0x989680;\n\t" \
            "@P1 bra.uni WAIT_DONE_%=;\n\t" \
            "bra.uni WAIT_LOOP_%=;\n\t" \
            "WAIT_DONE_%=:\n\t}" \
            :: "r"(_mbar), "r"(_parity) : "memory"); \
    } \
} while(0)
#define TCGEN05_LD_32X32B_X32(r, tmem_addr) \
    asm volatile( \
        "tcgen05.ld.sync.aligned.32x32b.x32.b32 " \
        "{%0, %1, %2, %3, %4, %5, %6, %7, " \
        " %8, %9, %10, %11, %12, %13, %14, %15, " \
        " %16, %17, %18, %19, %20, %21, %22, %23, " \
        " %24, %25, %26, %27, %28, %29, %30, %31}, [%32];" \
        : "=r"((r)[0]),  "=r"((r)[1]),  "=r"((r)[2]),  "=r"((r)[3]), \
          "=r"((r)[4]),  "=r"((r)[5]),  "=r"((r)[6]),  "=r"((r)[7]), \
          "=r"((r)[8]),  "=r"((r)[9]),  "=r"((r)[10]), "=r"((r)[11]), \
          "=r"((r)[12]), "=r"((r)[13]), "=r"((r)[14]), "=r"((r)[15]), \
          "=r"((r)[16]), "=r"((r)[17]), "=r"((r)[18]), "=r"((r)[19]), \
          "=r"((r)[20]), "=r"((r)[21]), "=r"((r)[22]), "=r"((r)[23]), \
          "=r"((r)[24]), "=r"((r)[25]), "=r"((r)[26]), "=r"((r)[27]), \
          "=r"((r)[28]), "=r"((r)[29]), "=r"((r)[30]), "=r"((r)[31]) \
        : "r"(tmem_addr))
__device__ __forceinline__ void mma_tf32_t05(uint32_t d, uint64_t a, uint64_t b,
                                             uint32_t idesc, uint32_t en) {
    asm volatile(
        "{\n\t.reg .pred p;\n\tsetp.ne.u32 p, %4, 0;\n\t"
        "tcgen05.mma.cta_group::1.kind::tf32 [%0], %1, %2, %3, p;\n\t}"
        :: "r"(d), "l"(a), "l"(b), "r"(idesc), "r"(en) : "memory");
}
__device__ __forceinline__ float tf32r(float x) {
    float y;
    asm("cvt.rna.tf32.f32 %0, %1;" : "=f"(y) : "f"(x));
    return y;
}
#define GT_IDESC ((1u<<4)|(2u<<7)|(2u<<10)|((128u/8)<<17)|((128u/16)<<24))
#endif // HAVE_TCGEN05

// ================= GEMM =====================================================
// C[m,n] = sum_k A[m,k]*B[n,k]; A:[M,K], B:[N,K] row-major fp32. 3xTF32.
#define GB_M 128
#define GB_N 128
#define GB_K 32
#define GB_SMEM_BYTES 136192       // covers both paths

__global__ __launch_bounds__(256, 1) void gemm_tf32x3(
    const float* __restrict__ A, const float* __restrict__ B,
    float* __restrict__ C, int M, int N, int K)
{
    extern __shared__ char smem[];
    const int tid = threadIdx.x;
    const int bm  = blockIdx.y * GB_M;
    const int bn  = blockIdx.x * GB_N;
    const int nch = K / GB_K;

#if HAVE_TCGEN05
    // ------------- tcgen05 SS-mode 3xTF32 pipeline -------------
    const uint32_t sb = smem_to_u32(smem);
    const int wid = tid >> 5;
    const int lid = tid & 31;
    const uint32_t OFF_TMEM = 0;
    const uint32_t OFF_MBAR = 8;
    const uint32_t OFF_TILE = 1024;
    const uint32_t STAGE = 65536;

    if (wid == 0) TCGEN05_ALLOC(sb + OFF_TMEM, 128);
    if (tid == 0) {
        MBARRIER_INIT(sb + OFF_MBAR, 1);
        MBARRIER_INIT(sb + OFF_MBAR + 8, 1);
    }
    __syncthreads();
    uint32_t tmem;
    asm volatile("ld.shared.b32 %0, [%1];" : "=r"(tmem) : "r"(sb + OFF_TMEM));

    const int lrow = tid >> 1;
    const int lcol = (tid & 1) * 16;
    const float* Aptr = A + (size_t)(bm + lrow) * K + lcol;
    const bool bvalid = (bn + lrow) < N;
    const float* Bptr = B + (size_t)((bn + lrow) < N ? (bn + lrow) : (N - 1)) * K + lcol;

    float4 ra[4], rb[4];
    auto ldg_chunk = [&](int kt) {
        #pragma unroll
        for (int i = 0; i < 4; i++) {
            ra[i] = *(const float4*)(Aptr + kt + i * 4);
            rb[i] = bvalid ? *(const float4*)(Bptr + kt + i * 4)
                           : make_float4(0.f, 0.f, 0.f, 0.f);
        }
    };
    auto sts_chunk = [&](int s) {
        char* base = smem + OFF_TILE + s * STAGE;
        const uint32_t ro = (uint32_t)(lrow * 128 + lcol * 4);
        #pragma unroll
        for (int i = 0; i < 4; i++) {
            uint32_t off = SMEM_SWIZZLE_128B(ro + i * 16);
            float4 v = ra[i];
            float4 hi = make_float4(tf32r(v.x), tf32r(v.y), tf32r(v.z), tf32r(v.w));
            float4 lo = make_float4(tf32r(v.x - hi.x), tf32r(v.y - hi.y),
                                    tf32r(v.z - hi.z), tf32r(v.w - hi.w));
            *(float4*)(base + off)         = hi;
            *(float4*)(base + 16384 + off) = lo;
            float4 w = rb[i];
            float4 bh = make_float4(tf32r(w.x), tf32r(w.y), tf32r(w.z), tf32r(w.w));
            float4 bl = make_float4(tf32r(w.x - bh.x), tf32r(w.y - bh.y),
                                    tf32r(w.z - bh.z), tf32r(w.w - bh.w));
            *(float4*)(base + 32768 + off) = bh;
            *(float4*)(base + 49152 + off) = bl;
        }
    };

    ldg_chunk(0);
    sts_chunk(0);
    if (nch > 1) ldg_chunk(GB_K);
    __syncthreads();

    bool first = true;
    for (int c = 0; c < nch; c++) {
        const int cur = c & 1;
        if (wid == 0 && elect_one_pred()) {
            FENCE_PROXY_ASYNC_SHARED_CTA();
            uint32_t base = sb + OFF_TILE + cur * STAGE;
            uint64_t dAhi = MAKE_SMEM_DESC(base);
            uint64_t dAlo = MAKE_SMEM_DESC(base + 16384);
            uint64_t dBhi = MAKE_SMEM_DESC(base + 32768);
            uint64_t dBlo = MAKE_SMEM_DESC(base + 49152);
            #pragma unroll
            for (int ks = 0; ks < 4; ks++) {
                mma_tf32_t05(tmem, dAhi + ks * 2, dBhi + ks * 2, GT_IDESC, first ? 0u : 1u);
                first = false;
                mma_tf32_t05(tmem, dAhi + ks * 2, dBlo + ks * 2, GT_IDESC, 1u);
                mma_tf32_t05(tmem, dAlo + ks * 2, dBhi + ks * 2, GT_IDESC, 1u);
            }
            TCGEN05_COMMIT(sb + OFF_MBAR + cur * 8);
        }
        const int nxt = cur ^ 1;
        if (c + 1 < nch) {
            if (c >= 1) MBARRIER_WAIT_PARITY(sb + OFF_MBAR + nxt * 8, ((c - 1) >> 1) & 1);
            sts_chunk(nxt);
            if (c + 2 < nch) ldg_chunk((c + 2) * GB_K);
        }
        __syncthreads();
    }
    {
        const int ls = (nch - 1) & 1;
        MBARRIER_WAIT_PARITY(sb + OFF_MBAR + ls * 8, ((nch - 1) >> 1) & 1);
    }
    TCGEN05_FENCE_AFTER();

    if (wid < 4) {
        const int row = bm + wid * 32 + lid;
        const size_t rbase = (size_t)row * N;
        #pragma unroll
        for (int cb = 0; cb < 4; cb++) {
            uint32_t d[32];
            TCGEN05_LD_32X32B_X32(d, tmem + cb * 32);
            TCGEN05_WAIT_LD();
            #pragma unroll
            for (int j = 0; j < 32; j += 4) {
                int col = bn + cb * 32 + j;
                if (col + 4 <= N) {
                    float4 v = make_float4(__uint_as_float(d[j]),
                                           __uint_as_float(d[j + 1]),
                                           __uint_as_float(d[j + 2]),
                                           __uint_as_float(d[j + 3]));
                    *(float4*)(C + rbase + col) = v;
                }
            }
        }
        TCGEN05_FENCE_BEFORE();
    }
    __syncthreads();
    if (wid == 0) TCGEN05_DEALLOC(tmem, 128);

#else
    // ------------- mma.sync m16n8k8 tf32 path (plain sm_103) -------------
    // smem: As[2][128][36], Bs[2][128][36]
    float* As = (float*)smem;
    float* Bs = As + 2 * 128 * 36;
    const uint32_t sA = smem_to_u32(As);
    const uint32_t sB = smem_to_u32(Bs);

    const int warp = tid >> 5;
    const int lane = tid & 31;
    const int wm = warp >> 2;     // 0..1
    const int wn = warp & 3;      // 0..3

    float acc[4][4][4];
    #pragma unroll
    for (int mt = 0; mt < 4; mt++)
        #pragma unroll
        for (int nt = 0; nt < 4; nt++)
            #pragma unroll
            for (int q = 0; q < 4; q++) acc[mt][nt][q] = 0.f;

    auto load_stage = [&](int buf, int kt) {
        #pragma unroll
        for (int i = 0; i < 4; i++) {
            int idx = tid + i * 256;     // 0..1023
            int row = idx >> 3, q = idx & 7;
            uint32_t sa = sA + (uint32_t)(buf * 128 * 36 + row * 36 + q * 4) * 4;
            const float* g = A + (size_t)(bm + row) * K + kt + q * 4;
            asm volatile("cp.async.cg.shared.global [%0], [%1], 16;"
                         :: "r"(sa), "l"(g));
        }
        #pragma unroll
        for (int i = 0; i < 4; i++) {
            int idx = tid + i * 256;
            int row = idx >> 3, q = idx & 7;
            int gn = bn + row; if (gn >= N) gn = N - 1;
            uint32_t sbb = sB + (uint32_t)(buf * 128 * 36 + row * 36 + q * 4) * 4;
            const float* g = B + (size_t)gn * K + kt + q * 4;
            asm volatile("cp.async.cg.shared.global [%0], [%1], 16;"
                         :: "r"(sbb), "l"(g));
        }
        asm volatile("cp.async.commit_group;");
    };

    load_stage(0, 0);
    if (nch > 1) load_stage(1, GB_K);

    const int lr = lane >> 2;     // 0..7
    const int lc = lane & 3;      // 0..3

    for (int c = 0; c < nch; c++) {
        if (c + 1 < nch) asm volatile("cp.async.wait_group 1;");
        else             asm volatile("cp.async.wait_group 0;");
        __syncthreads();

        const int abase = (c & 1) * 128 * 36;
        const int bbase = (c & 1) * 128 * 36;

        #pragma unroll
        for (int ks = 0; ks < 4; ks++) {
            uint32_t ahi[4][4], alo[4][4];
            #pragma unroll
            for (int mt = 0; mt < 4; mt++) {
                int r0 = wm * 64 + mt * 16 + lr;
                int k0 = ks * 8 + lc;
                split_tf32(As[abase + r0 * 36 + k0],        ahi[mt][0], alo[mt][0]);
                split_tf32(As[abase + (r0 + 8) * 36 + k0],  ahi[mt][1], alo[mt][1]);
                split_tf32(As[abase + r0 * 36 + k0 + 4],    ahi[mt][2], alo[mt][2]);
                split_tf32(As[abase + (r0 + 8) * 36 + k0 + 4], ahi[mt][3], alo[mt][3]);
            }
            uint32_t bhi[4][2], blo[4][2];
            #pragma unroll
            for (int nt = 0; nt < 4; nt++) {
                int n0 = wn * 32 + nt * 8 + lr;
                int k0 = ks * 8 + lc;
                split_tf32(Bs[bbase + n0 * 36 + k0],     bhi[nt][0], blo[nt][0]);
                split_tf32(Bs[bbase + n0 * 36 + k0 + 4], bhi[nt][1], blo[nt][1]);
            }
            #pragma unroll
            for (int mt = 0; mt < 4; mt++)
                #pragma unroll
                for (int nt = 0; nt < 4; nt++) {
                    mma_16n8k8(acc[mt][nt], ahi[mt], bhi[nt]);
                    mma_16n8k8(acc[mt][nt], ahi[mt], blo[nt]);
                    mma_16n8k8(acc[mt][nt], alo[mt], bhi[nt]);
                }
        }
        __syncthreads();
        if (c + 2 < nch) load_stage(c & 1, (c + 2) * GB_K);
    }

    // epilogue
    #pragma unroll
    for (int mt = 0; mt < 4; mt++) {
        int row = bm + wm * 64 + mt * 16 + lr;
        #pragma unroll
        for (int nt = 0; nt < 4; nt++) {
            int col = bn + wn * 32 + nt * 8 + lc * 2;
            if (col < N) {
                *(float2*)(C + (size_t)row * N + col) =
                    make_float2(acc[mt][nt][0], acc[mt][nt][1]);
                *(float2*)(C + (size_t)(row + 8) * N + col) =
                    make_float2(acc[mt][nt][2], acc[mt][nt][3]);
            }
        }
    }
#endif
}

// ---------------- depthwise causal conv (k=4) + bias + SiLU ----------------
__global__ __launch_bounds__(256) void conv_kernel(
    const float* __restrict__ zx, const float* __restrict__ cw,
    const float* __restrict__ cb, float* __restrict__ xbc)
{
    int c = blockIdx.x * 256 + threadIdx.x;
    if (c >= CONV_DIM) return;
    int strip = blockIdx.y;
    int b     = blockIdx.z;
    int l0    = strip * 256;

    float w0 = cw[c*4+0], w1 = cw[c*4+1], w2 = cw[c*4+2], w3 = cw[c*4+3];
    float bias = cb[c];

    size_t colbase = (size_t)D_INNER + c;
    size_t rb = (size_t)b * SEQLEN;

    float xm3 = (l0-3 >= 0) ? zx[(rb + l0-3) * D_IN_PROJ + colbase] : 0.f;
    float xm2 = (l0-2 >= 0) ? zx[(rb + l0-2) * D_IN_PROJ + colbase] : 0.f;
    float xm1 = (l0-1 >= 0) ? zx[(rb + l0-1) * D_IN_PROJ + colbase] : 0.f;

    for (int l = l0; l < l0 + 256; l++) {
        float xv = zx[(rb + l) * D_IN_PROJ + colbase];
        float a = bias;
        a = fmaf(w0, xm3, a);
        a = fmaf(w1, xm2, a);
        a = fmaf(w2, xm1, a);
        a = fmaf(w3, xv,  a);
        float sv = a / (1.f + expf(-a));
        xbc[(rb + l) * CONV_DIM + c] = sv;
        xm3 = xm2; xm2 = xm1; xm1 = xv;
    }
}

// ---------------- dt -> softplus -> decay ----------------------------------
__global__ __launch_bounds__(256) void decay_kernel(
    const float* __restrict__ zx, const float* __restrict__ dt_bias,
    const float* __restrict__ A_log, float* __restrict__ dec)
{
    int idx = blockIdx.x * 256 + threadIdx.x;
    if (idx >= NROWS * NHEADS) return;
    int r = idx >> 4;
    int h = idx & 15;
    float raw = zx[(size_t)r * D_IN_PROJ + (D_IN_PROJ - NHEADS) + h] + dt_bias[h];
    float sp  = (raw > 20.f) ? raw : log1pf(expf(raw));
    float A   = -expf(A_log[h]);
    dec[idx]  = expf(sp * A);
}

// ---------------- sequential SSM scan --------------------------------------
__global__ __launch_bounds__(128) void scan_kernel(
    const float* __restrict__ xbc, const float* __restrict__ dec,
    const float* __restrict__ Dvec, float* __restrict__ yout)
{
    const int pb = blockIdx.x;
    const int h  = blockIdx.y;
    const int b  = blockIdx.z;
    const int tid = threadIdx.x;
    const int pl = tid >> 2;
    const int nq = tid & 3;

    __shared__ float sB[2][64], sC[2][64], sx[2][32];
    __shared__ float sdec[2];

    float s[16];
    #pragma unroll
    for (int j = 0; j < 16; j++) s[j] = 0.f;
    const float Dh = Dvec[h];

    const size_t base = (size_t)b * SEQLEN;
    const int xcol = h * HEADDIM + pb * 32;

    float r0 = 0.f, r1 = 0.f, rdec = 0.f;

    auto ld_regs = [&](int l) {
        size_t row = (base + l) * CONV_DIM;
        if (tid < 64)       r0 = xbc[row + D_INNER + tid];
        else                r0 = xbc[row + D_INNER + 64 + (tid - 64)];
        if (tid < 32)       r1 = xbc[row + xcol + tid];
        if (tid == 127)     rdec = dec[(base + l) * NHEADS + h];
    };
    auto sts = [&](int buf) {
        if (tid < 64)   sB[buf][tid] = r0;
        else            sC[buf][tid - 64] = r0;
        if (tid < 32)   sx[buf][tid] = r1;
        if (tid == 127) sdec[buf] = rdec;
    };

    ld_regs(0); sts(0);
    ld_regs(1);
    __syncthreads();

    for (int l = 0; l < SEQLEN; l++) {
        int cur = l & 1;
        if (l + 1 < SEQLEN) sts(cur ^ 1);
        if (l + 2 < SEQLEN) ld_regs(l + 2);

        float dcy = sdec[cur];
        float xv  = sx[cur][pl];
        const float4* B4 = (const float4*)&sB[cur][nq * 16];
        const float4* C4 = (const float4*)&sC[cur][nq * 16];

        float y = 0.f;
        #pragma unroll
        for (int q = 0; q < 4; q++) {
            float4 bq = B4[q];
            float4 cq = C4[q];
            s[q*4+0] = fmaf(s[q*4+0], dcy, bq.x * xv);  y = fmaf(s[q*4+0], cq.x, y);
            s[q*4+1] = fmaf(s[q*4+1], dcy, bq.y * xv);  y = fmaf(s[q*4+1], cq.y, y);
            s[q*4+2] = fmaf(s[q*4+2], dcy, bq.z * xv);  y = fmaf(s[q*4+2], cq.z, y);
            s[q*4+3] = fmaf(s[q*4+3], dcy, bq.w * xv);  y = fmaf(s[q*4+3], cq.w, y);
        }
        y += __shfl_xor_sync(0xffffffffu, y, 1);
        y += __shfl_xor_sync(0xffffffffu, y, 2);
        if (nq == 0)
            yout[(base + l) * D_INNER + xcol + pl] = fmaf(Dh, xv, y);
        __syncthreads();
    }
}

// ---------------- RMSNorm + sigmoid(z) gate --------------------------------
__global__ __launch_bounds__(256) void rms_gate_kernel(
    const float* __restrict__ y, const float* __restrict__ zx,
    const float* __restrict__ rmsw, float* __restrict__ yg)
{
    int r = blockIdx.x;
    const float*  yr = y  + (size_t)r * D_INNER;
    const float*  zr = zx + (size_t)r * D_IN_PROJ;
    const float4* y4 = (const float4*)yr;

    int tid = threadIdx.x;
    float ss = 0.f;
    #pragma unroll
    for (int i = 0; i < 2; i++) {
        float4 v = y4[tid + i * 256];
        ss += v.x*v.x + v.y*v.y + v.z*v.z + v.w*v.w;
    }
    #pragma unroll
    for (int o = 16; o > 0; o >>= 1) ss += __shfl_xor_sync(0xffffffffu, ss, o);
    __shared__ float red[8];
    if ((tid & 31) == 0) red[tid >> 5] = ss;
    __syncthreads();
    if (tid == 0) {
        float t = 0.f;
        #pragma unroll
        for (int i = 0; i < 8; i++) t += red[i];
        red[0] = rsqrtf(t * (1.f / D_INNER) + RMS_EPS);
    }
    __syncthreads();
    float rs = red[0];

    const float4* z4 = (const float4*)zr;
    const float4* w4 = (const float4*)rmsw;
    float4*       g4 = (float4*)(yg + (size_t)r * D_INNER);
    #pragma unroll
    for (int i = 0; i < 2; i++) {
        int c = tid + i * 256;
        float4 v = y4[c];
        float4 z = z4[c];
        float4 w = w4[c];
        float4 o;
        o.x = v.x * rs * w.x * (1.f / (1.f + expf(-z.x)));
        o.y = v.y * rs * w.y * (1.f / (1.f + expf(-z.y)));
        o.z = v.z * rs * w.z * (1.f / (1.f + expf(-z.z)));
        o.w = v.w * rs * w.w * (1.f / (1.f + expf(-z.w)));
        g4[c] = o;
    }
}

// ---------------- launcher -------------------------------------------------
extern "C" void kernel_launch(void* const* d_in, const int* in_sizes, int n_in,
                              void* d_out, int out_size)
{
    const float* u        = (const float*)d_in[0];
    const float* in_proj  = (const float*)d_in[1];
    const float* conv_w   = (const float*)d_in[2];
    const float* conv_b   = (const float*)d_in[3];
    const float* dt_bias  = (const float*)d_in[4];
    const float* A_log    = (const float*)d_in[5];
    const float* Dv       = (const float*)d_in[6];
    const float* rms_w    = (const float*)d_in[7];
    const float* out_w    = (const float*)d_in[8];
    float* out = (float*)d_out;

    float *zx, *xbc, *dec, *y, *yg;
    cudaGetSymbolAddress((void**)&zx,  g_zx);
    cudaGetSymbolAddress((void**)&xbc, g_xbc);
    cudaGetSymbolAddress((void**)&dec, g_dec);
    cudaGetSymbolAddress((void**)&y,   g_y);
    cudaGetSymbolAddress((void**)&yg,  g_yg);

    cudaFuncSetAttribute(gemm_tf32x3,
        cudaFuncAttributeMaxDynamicSharedMemorySize, GB_SMEM_BYTES);

    // 1) in_proj: zx[8192,4240] = u @ in_proj^T
    {
        dim3 grid((D_IN_PROJ + GB_N - 1) / GB_N, NROWS / GB_M);
        gemm_tf32x3<<<grid, 256, GB_SMEM_BYTES>>>(u, in_proj, zx,
                                                  NROWS, D_IN_PROJ, D_MODEL);
    }
    // 2) conv + silu
    {
        dim3 grid((CONV_DIM + 255) / 256, SEQLEN / 256, BATCH);
        conv_kernel<<<grid, 256>>>(zx, conv_w, conv_b, xbc);
    }
    // 3) decay precompute
    decay_kernel<<<(NROWS * NHEADS + 255) / 256, 256>>>(zx, dt_bias, A_log, dec);
    // 4) SSM scan
    {
        dim3 grid(HEADDIM / 32, NHEADS, BATCH);
        scan_kernel<<<grid, 128>>>(xbc, dec, Dv, y);
    }
    // 5) rmsnorm + gate
    rms_gate_kernel<<<NROWS, 256>>>(y, zx, rms_w, yg);
    // 6) out_proj
    {
        dim3 grid(D_MODEL / GB_N, NROWS / GB_M);
        gemm_tf32x3<<<grid, 256, GB_SMEM_BYTES>>>(yg, out_w, out,
                                                  NROWS, D_MODEL, D_INNER);
    }
}